// round 3
// baseline (speedup 1.0000x reference)
#include <cuda_runtime.h>
#include <cuda_bf16.h>

// Shapes (fixed by the problem):
//   se_pred: [64, 6]  float32   (384 elems)
//   target : [64, 512, 512] labels 0..5, delivered as int32 (16777216 elems)
//   out    : scalar float32 mean BCE loss
#define NBATCH     64
#define NCLASS     6
#define PIX        (512 * 512)          // 262144 labels per batch
#define BLK_PER_B  32
#define THREADS    256
// per chunk: PIX / BLK_PER_B = 8192 labels = 2048 int4
// per thread: 2048 / THREADS = 8 int4 loads (32 labels)
#define ITERS      8

// Per-block partial presence masks. Written unconditionally every launch
// (no zeroing pass, no atomics needed).
__device__ int g_partial[NBATCH * BLK_PER_B];

__global__ void __launch_bounds__(THREADS)
se_scan_kernel(const int* __restrict__ target) {
    const int b   = blockIdx.x >> 5;        // batch index
    const int blk = blockIdx.x & 31;        // chunk within batch
    const int4* __restrict__ base =
        (const int4*)(target + (size_t)b * PIX + (size_t)blk * (PIX / BLK_PER_B));

    const int tid = threadIdx.x;
    int mask = 0;

    // Coalesced 16B loads; early exit once all 6 classes seen locally.
    #pragma unroll 1
    for (int i = 0; i < ITERS; ++i) {
        int4 v = base[tid + i * THREADS];
        mask |= (1 << v.x) | (1 << v.y) | (1 << v.z) | (1 << v.w);
        if (mask == 0x3F) break;
    }

    // Warp OR-reduce, then block OR via shared.
    mask = __reduce_or_sync(0xFFFFFFFFu, mask);
    __shared__ int smask[THREADS / 32];
    if ((tid & 31) == 0) smask[tid >> 5] = mask;
    __syncthreads();
    if (tid == 0) {
        int m = 0;
        #pragma unroll
        for (int w = 0; w < THREADS / 32; ++w) m |= smask[w];
        g_partial[blockIdx.x] = m;
    }
}

__global__ void __launch_bounds__(256)
se_loss_kernel(const float* __restrict__ se_pred, float* __restrict__ out) {
    __shared__ int   pres[NBATCH];
    __shared__ float ssum[256];
    const int tid = threadIdx.x;

    if (tid < NBATCH) {
        int m = 0;
        #pragma unroll
        for (int i = 0; i < BLK_PER_B; ++i) m |= g_partial[tid * BLK_PER_B + i];
        pres[tid] = m;
    }
    __syncthreads();

    float s = 0.0f;
    for (int idx = tid; idx < NBATCH * NCLASS; idx += 256) {
        const int b = idx / NCLASS;
        const int c = idx - b * NCLASS;
        const float p = se_pred[idx];
        const float t = (float)((pres[b] >> c) & 1);
        // torch BCELoss clamps log at -100
        const float lp  = fmaxf(logf(p),      -100.0f);
        const float l1p = fmaxf(log1pf(-p),   -100.0f);
        s -= t * lp + (1.0f - t) * l1p;
    }
    ssum[tid] = s;
    __syncthreads();
    #pragma unroll
    for (int o = 128; o > 0; o >>= 1) {
        if (tid < o) ssum[tid] += ssum[tid + o];
        __syncthreads();
    }
    if (tid == 0) out[0] = ssum[0] * (1.0f / (NBATCH * NCLASS));
}

extern "C" void kernel_launch(void* const* d_in, const int* in_sizes, int n_in,
                              void* d_out, int out_size) {
    // Robust to input ordering: identify by element count.
    const float* se_pred;
    const int*   target;
    if (in_sizes[0] == NBATCH * NCLASS) {
        se_pred = (const float*)d_in[0];
        target  = (const int*)d_in[1];
    } else {
        se_pred = (const float*)d_in[1];
        target  = (const int*)d_in[0];
    }
    float* out = (float*)d_out;

    se_scan_kernel<<<NBATCH * BLK_PER_B, THREADS>>>(target);
    se_loss_kernel<<<1, 256>>>(se_pred, out);
}

// round 4
// speedup vs baseline: 1.1370x; 1.1370x over previous
#include <cuda_runtime.h>
#include <cuda_bf16.h>

// Shapes (fixed by the problem):
//   se_pred: [64, 6]  float32   (384 elems)
//   target : [64, 512, 512] labels 0..5, int32 on device (16777216 elems)
//   out    : scalar float32 mean BCE loss
#define NBATCH     64
#define NCLASS     6
#define PIX        (512 * 512)              // 262144 labels per batch
#define BLK_PER_B  8
#define NBLOCKS    (NBATCH * BLK_PER_B)     // 512
#define THREADS    256
// per chunk: PIX/BLK_PER_B = 32768 labels = 8192 int4; /256 threads = 32 int4 each
#define ITERS      32

// Per-block partial presence masks, written unconditionally each launch.
__device__ int g_partial[NBLOCKS];
// Last-block-done counter; last block resets it -> deterministic across replays.
__device__ unsigned g_count = 0;

__global__ void __launch_bounds__(THREADS)
se_fused_kernel(const int* __restrict__ target,
                const float* __restrict__ se_pred,
                float* __restrict__ out) {
    const int b   = blockIdx.x >> 3;        // batch index
    const int blk = blockIdx.x & 7;         // chunk within batch
    const int4* __restrict__ base =
        (const int4*)(target + (size_t)b * PIX + (size_t)blk * (PIX / BLK_PER_B));

    const int tid = threadIdx.x;
    int mask = 0;

    // Coalesced 16B loads. Warp-cooperative early exit: after each iteration
    // the warp's union covers 128 random labels -> P(exit after iter 0) ~ 1-4e-10.
    #pragma unroll 1
    for (int i = 0; i < ITERS; ++i) {
        int4 v = base[tid + i * THREADS];
        mask |= (1 << v.x) | (1 << v.y) | (1 << v.z) | (1 << v.w);
        mask = __reduce_or_sync(0xFFFFFFFFu, mask);   // warp union (uniform)
        if (mask == 0x3F) break;
    }

    // Block OR via shared, publish partial, last-block election.
    __shared__ int      smask[THREADS / 32];
    __shared__ bool     s_last;
    if ((tid & 31) == 0) smask[tid >> 5] = mask;
    __syncthreads();
    if (tid == 0) {
        int m = 0;
        #pragma unroll
        for (int w = 0; w < THREADS / 32; ++w) m |= smask[w];
        g_partial[blockIdx.x] = m;
        __threadfence();
        unsigned t = atomicAdd(&g_count, 1u);
        s_last = (t == NBLOCKS - 1);
    }
    __syncthreads();
    if (!s_last) return;

    // ---- Last block: epilogue ----
    if (tid == 0) g_count = 0;              // reset for next graph replay

    __shared__ int   pres[NBATCH];
    __shared__ float ssum[THREADS];
    if (tid < NBATCH) {
        const volatile int* gp = g_partial;
        int m = 0;
        #pragma unroll
        for (int i = 0; i < BLK_PER_B; ++i) m |= gp[tid * BLK_PER_B + i];
        pres[tid] = m;
    }
    __syncthreads();

    float s = 0.0f;
    for (int idx = tid; idx < NBATCH * NCLASS; idx += THREADS) {
        const int bi = idx / NCLASS;
        const int c  = idx - bi * NCLASS;
        const float p = se_pred[idx];
        const float t = (float)((pres[bi] >> c) & 1);
        // torch BCELoss clamps log at -100
        const float lp  = fmaxf(logf(p),    -100.0f);
        const float l1p = fmaxf(log1pf(-p), -100.0f);
        s -= t * lp + (1.0f - t) * l1p;
    }
    ssum[tid] = s;
    __syncthreads();
    #pragma unroll
    for (int o = THREADS / 2; o > 0; o >>= 1) {
        if (tid < o) ssum[tid] += ssum[tid + o];
        __syncthreads();
    }
    if (tid == 0) out[0] = ssum[0] * (1.0f / (NBATCH * NCLASS));
}

extern "C" void kernel_launch(void* const* d_in, const int* in_sizes, int n_in,
                              void* d_out, int out_size) {
    // Robust to input ordering: identify by element count.
    const float* se_pred;
    const int*   target;
    if (in_sizes[0] == NBATCH * NCLASS) {
        se_pred = (const float*)d_in[0];
        target  = (const int*)d_in[1];
    } else {
        se_pred = (const float*)d_in[1];
        target  = (const int*)d_in[0];
    }
    float* out = (float*)d_out;

    se_fused_kernel<<<NBLOCKS, THREADS>>>(target, se_pred, out);
}

// round 5
// speedup vs baseline: 1.8841x; 1.6570x over previous
#include <cuda_runtime.h>
#include <cuda_bf16.h>

// Shapes (fixed by the problem):
//   se_pred: [64, 6]  float32   (384 elems)
//   target : [64, 512, 512] labels 0..5, int32 on device (16777216 elems)
//   out    : scalar float32 mean BCE loss
#define NBATCH   64
#define NCLASS   6
#define PIX      (512 * 512)     // 262144 labels per batch
#define THREADS  1024            // one half-warp (16 threads) per batch
#define MAX_IT   (PIX / 4 / 16)  // 4096: full coverage fallback

__global__ void __launch_bounds__(THREADS)
se_one_block_kernel(const int* __restrict__ target,
                    const float* __restrict__ se_pred,
                    float* __restrict__ out) {
    const int tid   = threadIdx.x;
    const int lane  = tid & 31;
    const int batch = tid >> 4;          // 64 half-warps -> 64 batches
    const int sub   = tid & 15;          // lane within half-warp
    const unsigned hm = (lane < 16) ? 0x0000FFFFu : 0xFFFF0000u;

    const int4* __restrict__ base = (const int4*)(target + (size_t)batch * PIX);

    // Each round: half-warp unions 64 random labels. P(not done after round 1)
    // ~ 5e-5 per batch. Loop bound covers the whole image for correctness.
    int mask = 0;
    #pragma unroll 1
    for (int i = 0; i < MAX_IT; ++i) {
        int4 v = base[i * 16 + sub];
        mask |= (1 << v.x) | (1 << v.y) | (1 << v.z) | (1 << v.w);
        mask = __reduce_or_sync(hm, mask);   // uniform within half-warp
        if (mask == 0x3F) break;
    }

    __shared__ int   pres[NBATCH];
    __shared__ float sterm[NBATCH * NCLASS];
    if (sub == 0) pres[batch] = mask;
    __syncthreads();

    // 384 BCE terms, one per thread (threads 0..383).
    if (tid < NBATCH * NCLASS) {
        const int bi = tid / NCLASS;
        const int c  = tid - bi * NCLASS;
        const float p = se_pred[tid];
        const float t = (float)((pres[bi] >> c) & 1);
        // torch BCELoss clamps log at -100
        const float lp  = fmaxf(logf(p),    -100.0f);
        const float l1p = fmaxf(log1pf(-p), -100.0f);
        sterm[tid] = -(t * lp + (1.0f - t) * l1p);
    }
    __syncthreads();

    // Warp 0 sums 384 floats: 12 per lane, then butterfly.
    if (tid < 32) {
        float s = 0.0f;
        #pragma unroll
        for (int i = 0; i < (NBATCH * NCLASS) / 32; ++i)
            s += sterm[tid + i * 32];
        #pragma unroll
        for (int o = 16; o > 0; o >>= 1)
            s += __shfl_xor_sync(0xFFFFFFFFu, s, o);
        if (tid == 0) out[0] = s * (1.0f / (NBATCH * NCLASS));
    }
}

extern "C" void kernel_launch(void* const* d_in, const int* in_sizes, int n_in,
                              void* d_out, int out_size) {
    // Robust to input ordering: identify by element count.
    const float* se_pred;
    const int*   target;
    if (in_sizes[0] == NBATCH * NCLASS) {
        se_pred = (const float*)d_in[0];
        target  = (const int*)d_in[1];
    } else {
        se_pred = (const float*)d_in[1];
        target  = (const int*)d_in[0];
    }
    float* out = (float*)d_out;

    se_one_block_kernel<<<1, THREADS>>>(target, se_pred, out);
}

// round 6
// speedup vs baseline: 1.9697x; 1.0455x over previous
#include <cuda_runtime.h>
#include <cuda_bf16.h>

// Shapes (fixed by the problem):
//   se_pred: [64, 6]  float32   (384 elems)
//   target : [64, 512, 512] labels 0..5, int32 on device (16777216 elems)
//   out    : scalar float32 mean BCE loss
#define NBATCH   64
#define NCLASS   6
#define PIX      (512 * 512)     // 262144 labels per batch
#define THREADS  1024            // one half-warp (16 threads) per batch
#define MAX_IT   (PIX / 4 / 16)  // 4096: full coverage fallback

__global__ void __launch_bounds__(THREADS)
se_one_block_kernel(const int* __restrict__ target,
                    const float* __restrict__ se_pred,
                    float* __restrict__ out) {
    const int tid   = threadIdx.x;
    const int lane  = tid & 31;
    const int batch = tid >> 4;          // 64 half-warps -> 64 batches
    const int sub   = tid & 15;          // lane within half-warp
    const unsigned hm = (lane < 16) ? 0x0000FFFFu : 0xFFFF0000u;

    // Prefetch this lane's prediction NOW so its LDG overlaps the target
    // DRAM latency (lanes 0..5 of each half-warp own the 6 classes).
    float p = 1.0f;
    if (sub < NCLASS) p = se_pred[batch * NCLASS + sub];

    const int4* __restrict__ base = (const int4*)(target + (size_t)batch * PIX);

    // Each round: half-warp unions 64 random labels. P(not done after round 1)
    // ~ 5e-5 per batch. Loop bound covers the whole image for correctness.
    int mask = 0;
    #pragma unroll 1
    for (int i = 0; i < MAX_IT; ++i) {
        int4 v = base[i * 16 + sub];
        mask |= (1 << v.x) | (1 << v.y) | (1 << v.z) | (1 << v.w);
        mask = __reduce_or_sync(hm, mask);   // uniform within half-warp
        if (mask == 0x3F) break;
    }

    // Per-lane BCE term (lanes 0..5), then half-warp butterfly reduce.
    float s = 0.0f;
    if (sub < NCLASS) {
        const float t   = (float)((mask >> sub) & 1);
        // torch BCELoss clamps log at -100
        const float lp  = fmaxf(logf(p),    -100.0f);
        const float l1p = fmaxf(log1pf(-p), -100.0f);
        s = -(t * lp + (1.0f - t) * l1p);
    }
    #pragma unroll
    for (int o = 8; o > 0; o >>= 1)
        s += __shfl_xor_sync(hm, s, o);      // offsets 1,2,4,8 stay in half-warp

    __shared__ float part[NBATCH];
    if (sub == 0) part[batch] = s;
    __syncthreads();

    // Warp 0 sums the 64 batch partials.
    if (tid < 32) {
        float v = part[tid] + part[tid + 32];
        #pragma unroll
        for (int o = 16; o > 0; o >>= 1)
            v += __shfl_xor_sync(0xFFFFFFFFu, v, o);
        if (tid == 0) out[0] = v * (1.0f / (NBATCH * NCLASS));
    }
}

extern "C" void kernel_launch(void* const* d_in, const int* in_sizes, int n_in,
                              void* d_out, int out_size) {
    // Robust to input ordering: identify by element count.
    const float* se_pred;
    const int*   target;
    if (in_sizes[0] == NBATCH * NCLASS) {
        se_pred = (const float*)d_in[0];
        target  = (const int*)d_in[1];
    } else {
        se_pred = (const float*)d_in[1];
        target  = (const int*)d_in[0];
    }
    float* out = (float*)d_out;

    se_one_block_kernel<<<1, THREADS>>>(target, se_pred, out);
}